// round 8
// baseline (speedup 1.0000x reference)
#include <cuda_runtime.h>
#include <cuda_bf16.h>
#include <stdint.h>

// ----------------------------------------------------------------------------
// SpectralPooling via HMMA (mma.sync m16n8k16 bf16, 3-term split) GEMMs.
// y = idctn(pad(crop(dctn(x)))); axes 0,1 cancel. Per-axis operator
// B[o][i] = sum_{k<28} D32[k,o]*D64[k,i]  (32x64), applied along axes 2,3,4.
// Three stages, each GEMM [rows x 64] -> [rows x 32] against B^T; outputs are
// written "pre-transposed" so K is always contiguous and stores coalesce:
//   stage1 (SB=12): X[b][i0][i1][i2]   -> T1[b][o2][i0][i1]
//   stage2 (SB=11): T1[b][o2][i0][i1]  -> T2[b][o1][o2][i0]
//   stage3 (SB=10): T2[b][o1][o2][i0]  -> Y[b][o0][o1][o2]
// out_addr(m,c) = (m>>SB)*(32<<SB) + c*(1<<SB) + (m & ((1<<SB)-1))
// Precision: D = Ah*Bh + Ah*Bl + Al*Bh (bf16 hi/lo splits, fp32 accumulate).
// B fragments preloaded to REGISTERS once per CTA (64 regs/warp); mainloop
// smem traffic is A-only. Grid-stride tile loop amortizes B + launch cost.
// ----------------------------------------------------------------------------

__device__ __nv_bfloat16 g_Bh[2048];   // B hi, row-major [o][i] (32x64)
__device__ __nv_bfloat16 g_Bl[2048];   // B lo
__device__ float g_T1[33554432];       // 128 MB scratch
__device__ float g_T2[16777216];       //  64 MB scratch

__device__ __forceinline__ uint32_t smem_u32(const void* p) {
    uint32_t a;
    asm("{ .reg .u64 t; cvta.to.shared.u64 t, %1; cvt.u32.u64 %0, t; }"
        : "=r"(a) : "l"(p));
    return a;
}

// ---------------- init: one warp per B element, lane = k-term -------------------
__global__ void init_B_kernel() {
    int gw   = (blockIdx.x * blockDim.x + threadIdx.x) >> 5;  // 0..2047
    int lane = threadIdx.x & 31;
    if (gw >= 2048) return;
    int o = gw >> 6;   // 0..31
    int i = gw & 63;   // 0..63
    float term = 0.0f;
    if (lane < 28) {
        const float s32_0 = 0.17677669529663688f;  // sqrt(1/32)
        const float s32_k = 0.25f;                 // sqrt(2/32)
        const float s64_0 = 0.125f;                // sqrt(1/64)
        const float s64_k = 0.17677669529663688f;  // sqrt(2/64)
        float a32 = (2.0f * o + 1.0f) * (float)lane / 64.0f;
        float a64 = (2.0f * i + 1.0f) * (float)lane / 128.0f;
        float d32 = ((lane == 0) ? s32_0 : s32_k) * cospif(a32);
        float d64 = ((lane == 0) ? s64_0 : s64_k) * cospif(a64);
        term = d32 * d64;
    }
    #pragma unroll
    for (int s = 16; s > 0; s >>= 1)
        term += __shfl_xor_sync(0xFFFFFFFFu, term, s);
    if (lane == 0) {
        __nv_bfloat16 h = __float2bfloat16(term);
        float lo = term - __bfloat162float(h);
        g_Bh[gw] = h;
        g_Bl[gw] = __float2bfloat16(lo);
    }
}

// ---------------- mma.sync / ldmatrix wrappers ------------------------------------
__device__ __forceinline__ void mma16816(float* d, const uint32_t* a,
                                         const uint32_t* b) {
    asm("mma.sync.aligned.m16n8k16.row.col.f32.bf16.bf16.f32 "
        "{%0,%1,%2,%3}, {%4,%5,%6,%7}, {%8,%9}, {%0,%1,%2,%3};"
        : "+f"(d[0]), "+f"(d[1]), "+f"(d[2]), "+f"(d[3])
        : "r"(a[0]), "r"(a[1]), "r"(a[2]), "r"(a[3]), "r"(b[0]), "r"(b[1]));
}

__device__ __forceinline__ void ldsm4(uint32_t* r, uint32_t addr) {
    asm volatile("ldmatrix.sync.aligned.m8n8.x4.shared.b16 {%0,%1,%2,%3}, [%4];"
                 : "=r"(r[0]), "=r"(r[1]), "=r"(r[2]), "=r"(r[3]) : "r"(addr));
}

// ---------------- stage kernel --------------------------------------------------
// Grid-stride over M=64 tiles. Warp w: rows w*16..w*16+15, all 32 output cols.
// smem: sAh/sAl 9 KB each (A tile bf16 hi/lo, row stride 72 bf16).
// B is staged into the arena transiently, fragments kept in registers.
template<int SB>
__global__ __launch_bounds__(128, 4) void stage_kernel(
        const float* __restrict__ xin, float* __restrict__ xout) {
    const float* in = (SB == 12) ? xin : (SB == 11 ? (const float*)g_T1
                                                   : (const float*)g_T2);
    float* out      = (SB == 12) ? (float*)g_T1
                                 : (SB == 11 ? (float*)g_T2 : xout);
    constexpr size_t OC = (size_t)1 << SB;
    const int tiles = (SB == 12) ? 16384 : (SB == 11 ? 8192 : 4096);

    __shared__ __align__(16) __nv_bfloat16 sAh[64 * 72];   // 9 KB
    __shared__ __align__(16) __nv_bfloat16 sAl[64 * 72];   // 9 KB

    const int tid = threadIdx.x;
    const int w   = tid >> 5;
    const int lid = tid & 31;
    const int gid = lid >> 2;   // 0..7
    const int tg  = lid & 3;    // 0..3
    const int lr  = lid & 7, mi = lid >> 3;

    const uint32_t uAh = smem_u32(sAh), uAl = smem_u32(sAl);

    // ---- stage B into arena, preload fragments to registers, arena freed after
    uint32_t bfh[4][4][2], bfl[4][4][2];   // [kk][nt][reg]
    {
        const uint32_t* bh = (const uint32_t*)g_Bh;
        const uint32_t* bl = (const uint32_t*)g_Bl;
        #pragma unroll
        for (int idx = tid; idx < 1024; idx += 128) {
            int r = idx >> 5, c2 = idx & 31;
            *(uint32_t*)&sAh[r * 72 + c2 * 2] = bh[idx];   // B-hi staged in sAh
            *(uint32_t*)&sAl[r * 72 + c2 * 2] = bl[idx];   // B-lo staged in sAl
        }
        __syncthreads();
        const uint32_t boff0 =
            (uint32_t)(((mi >> 1) << 3) + lr) * 144u + ((mi & 1) << 4);
        #pragma unroll
        for (int kk = 0; kk < 4; ++kk)
            #pragma unroll
            for (int t = 0; t < 2; ++t) {
                uint32_t bo = boff0 + (uint32_t)(t * 16 * 144)
                                    + (uint32_t)(kk * 32);
                uint32_t rh[4], rl[4];
                ldsm4(rh, uAh + bo);
                ldsm4(rl, uAl + bo);
                bfh[kk][2 * t][0] = rh[0]; bfh[kk][2 * t][1] = rh[1];
                bfh[kk][2 * t + 1][0] = rh[2]; bfh[kk][2 * t + 1][1] = rh[3];
                bfl[kk][2 * t][0] = rl[0]; bfl[kk][2 * t][1] = rl[1];
                bfl[kk][2 * t + 1][0] = rl[2]; bfl[kk][2 * t + 1][1] = rl[3];
            }
    }

    const uint32_t aoff0 =
        (uint32_t)(w * 16 + ((mi & 1) << 3) + lr) * 144u + ((mi >> 1) << 4);

    // ---- tile loop
    for (int tt = blockIdx.x; tt < tiles; tt += gridDim.x) {
        __syncthreads();   // arena free (B frags read / prev epilogue done)

        // load A tile (1024 float4), split to bf16 hi/lo, padded smem
        {
            const float4* __restrict__ inp =
                (const float4*)(in + (size_t)tt * 4096);
            #pragma unroll
            for (int j = 0; j < 8; ++j) {
                int f = j * 128 + tid;
                float4 v = inp[f];
                int r = f >> 4, k4 = f & 15;
                uint32_t h01, h23, l01, l23;
                asm("cvt.rn.bf16x2.f32 %0, %1, %2;" : "=r"(h01)
                    : "f"(v.y), "f"(v.x));
                asm("cvt.rn.bf16x2.f32 %0, %1, %2;" : "=r"(h23)
                    : "f"(v.w), "f"(v.z));
                float hx = __uint_as_float(h01 << 16);
                float hy = __uint_as_float(h01 & 0xFFFF0000u);
                float hz = __uint_as_float(h23 << 16);
                float hw = __uint_as_float(h23 & 0xFFFF0000u);
                asm("cvt.rn.bf16x2.f32 %0, %1, %2;" : "=r"(l01)
                    : "f"(v.y - hy), "f"(v.x - hx));
                asm("cvt.rn.bf16x2.f32 %0, %1, %2;" : "=r"(l23)
                    : "f"(v.w - hw), "f"(v.z - hz));
                *(uint2*)&sAh[r * 72 + k4 * 4] = make_uint2(h01, h23);
                *(uint2*)&sAl[r * 72 + k4 * 4] = make_uint2(l01, l23);
            }
        }
        __syncthreads();

        // mainloop: A-only smem traffic
        float acc[4][4];
        #pragma unroll
        for (int nt = 0; nt < 4; ++nt)
            #pragma unroll
            for (int q = 0; q < 4; ++q) acc[nt][q] = 0.0f;

        #pragma unroll
        for (int kk = 0; kk < 4; ++kk) {
            uint32_t ah[4], al[4];
            uint32_t ao = aoff0 + (uint32_t)(kk * 32);
            ldsm4(ah, uAh + ao);
            ldsm4(al, uAl + ao);
            #pragma unroll
            for (int nt = 0; nt < 4; ++nt) {
                mma16816(acc[nt], ah, bfh[kk][nt]);   // Ah*Bh
                mma16816(acc[nt], ah, bfl[kk][nt]);   // Ah*Bl
                mma16816(acc[nt], al, bfh[kk][nt]);   // Al*Bh
            }
        }
        __syncthreads();   // all ldsm reads done before epilogue overwrites sAh

        // epilogue: CTA-wide transpose through dead sAh (64x33 fp32 = 8448 B)
        float* ep = (float*)sAh;
        #pragma unroll
        for (int nt = 0; nt < 4; ++nt)
            #pragma unroll
            for (int q = 0; q < 4; ++q) {
                int r = w * 16 + gid + ((q >> 1) << 3);
                int c = nt * 8 + tg * 2 + (q & 1);
                ep[r * 33 + c] = acc[nt][q];
            }
        __syncthreads();

        // coalesced transposed store: 16 values per thread
        float* __restrict__ ob = out
            + (size_t)(tt >> (SB - 6)) * (OC * 32)
            + (size_t)(((uint32_t)tt << 6) & (OC - 1));
        #pragma unroll
        for (int j = 0; j < 16; ++j) {
            int idx = j * 128 + tid;     // 0..2047
            int ml = idx & 63, c = idx >> 6;
            ob[(size_t)c * OC + (size_t)ml] = ep[ml * 33 + c];
        }
    }
}

// ---------------- launch ---------------------------------------------------------
extern "C" void kernel_launch(void* const* d_in, const int* in_sizes, int n_in,
                              void* d_out, int out_size) {
    const float* x = (const float*)d_in[0];
    float* out = (float*)d_out;

    init_B_kernel<<<512, 128>>>();

    stage_kernel<12><<<2048, 128>>>(x, out);   // X  -> T1   (contract i2)
    stage_kernel<11><<<2048, 128>>>(x, out);   // T1 -> T2   (contract i1)
    stage_kernel<10><<<2048, 128>>>(x, out);   // T2 -> out  (contract i0)
}

// round 10
// speedup vs baseline: 1.0326x; 1.0326x over previous
#include <cuda_runtime.h>
#include <cuda_bf16.h>
#include <stdint.h>

// ----------------------------------------------------------------------------
// SpectralPooling via HMMA (mma.sync m16n8k16 bf16, 3-term split) GEMMs.
// y = idctn(pad(crop(dctn(x)))); axes 0,1 cancel. Per-axis operator
// B[o][i] = sum_{k<28} D32[k,o]*D64[k,i]  (32x64), applied along axes 2,3,4.
// Three stages, each GEMM [rows x 64] -> [rows x 32] against B^T; outputs are
// written "pre-transposed" so K is always contiguous and stores coalesce:
//   stage1 (SB=12): X[b][i0][i1][i2]   -> T1[b][o2][i0][i1]   (8192 tiles)
//   stage2 (SB=11): T1[...]            -> T2[b][o1][o2][i0]   (4096 tiles)
//   stage3 (SB=10): T2[...]            -> Y[b][o0][o1][o2]    (2048 tiles)
// out_addr(m,c) = (m>>SB)*(32<<SB) + c*(1<<SB) + (m & ((1<<SB)-1))
// Intermediates T1,T2 stored as PLANAR bf16 hi/lo: stages 2,3 load tiles with
// cp.async (no conversion, no register pass); split happens in the epilogue.
// Stages 2,3 run 2 tiles/CTA: tile t+1's cp.async overlaps tile t's epilogue.
// Precision: D = Ah*Bh + Ah*Bl + Al*Bh (bf16 hi/lo splits, fp32 accumulate).
// ----------------------------------------------------------------------------

__device__ __nv_bfloat16 g_Bh[2048];       // B hi, row-major [o][i] (32x64)
__device__ __nv_bfloat16 g_Bl[2048];       // B lo
__device__ __nv_bfloat16 g_T1h[33554432];  // 64 MB
__device__ __nv_bfloat16 g_T1l[33554432];  // 64 MB
__device__ __nv_bfloat16 g_T2h[16777216];  // 32 MB
__device__ __nv_bfloat16 g_T2l[16777216];  // 32 MB

__device__ __forceinline__ uint32_t smem_u32(const void* p) {
    uint32_t a;
    asm("{ .reg .u64 t; cvta.to.shared.u64 t, %1; cvt.u32.u64 %0, t; }"
        : "=r"(a) : "l"(p));
    return a;
}

// ---------------- init ------------------------------------------------------------
__global__ void init_B_kernel() {
    int gw   = (blockIdx.x * blockDim.x + threadIdx.x) >> 5;
    int lane = threadIdx.x & 31;
    if (gw >= 2048) return;
    int o = gw >> 6, i = gw & 63;
    float term = 0.0f;
    if (lane < 28) {
        const float s32_0 = 0.17677669529663688f;
        const float s32_k = 0.25f;
        const float s64_0 = 0.125f;
        const float s64_k = 0.17677669529663688f;
        float a32 = (2.0f * o + 1.0f) * (float)lane / 64.0f;
        float a64 = (2.0f * i + 1.0f) * (float)lane / 128.0f;
        term = ((lane == 0) ? s32_0 : s32_k) * cospif(a32)
             * ((lane == 0) ? s64_0 : s64_k) * cospif(a64);
    }
    #pragma unroll
    for (int s = 16; s > 0; s >>= 1)
        term += __shfl_xor_sync(0xFFFFFFFFu, term, s);
    if (lane == 0) {
        __nv_bfloat16 h = __float2bfloat16(term);
        g_Bh[gw] = h;
        g_Bl[gw] = __float2bfloat16(term - __bfloat162float(h));
    }
}

// ---------------- wrappers ---------------------------------------------------------
__device__ __forceinline__ void mma16816(float* d, const uint32_t* a,
                                         const uint32_t* b) {
    asm("mma.sync.aligned.m16n8k16.row.col.f32.bf16.bf16.f32 "
        "{%0,%1,%2,%3}, {%4,%5,%6,%7}, {%8,%9}, {%0,%1,%2,%3};"
        : "+f"(d[0]), "+f"(d[1]), "+f"(d[2]), "+f"(d[3])
        : "r"(a[0]), "r"(a[1]), "r"(a[2]), "r"(a[3]), "r"(b[0]), "r"(b[1]));
}
__device__ __forceinline__ void ldsm4(uint32_t* r, uint32_t addr) {
    asm volatile("ldmatrix.sync.aligned.m8n8.x4.shared.b16 {%0,%1,%2,%3}, [%4];"
                 : "=r"(r[0]), "=r"(r[1]), "=r"(r[2]), "=r"(r[3]) : "r"(addr));
}
__device__ __forceinline__ void cp16(uint32_t dst, const void* src) {
    asm volatile("cp.async.cg.shared.global [%0], [%1], 16;"
                 :: "r"(dst), "l"(src) : "memory");
}
#define CP_COMMIT() asm volatile("cp.async.commit_group;" ::: "memory")
#define CP_WAIT0()  asm volatile("cp.async.wait_group 0;" ::: "memory")

// ---------------- mainloop (M=128 tile, 4 warps, warp = 32 rows) -------------------
__device__ __forceinline__ void mainloop128(float (&acc)[2][4][4],
        uint32_t uAh, uint32_t uAl, uint32_t uBh, uint32_t uBl,
        uint32_t aoff0, uint32_t boff0) {
    #pragma unroll
    for (int rt = 0; rt < 2; ++rt)
        #pragma unroll
        for (int nt = 0; nt < 4; ++nt)
            #pragma unroll
            for (int q = 0; q < 4; ++q) acc[rt][nt][q] = 0.0f;

    #pragma unroll
    for (int kk = 0; kk < 4; ++kk) {
        uint32_t ah[2][4], al[2][4];
        #pragma unroll
        for (int rt = 0; rt < 2; ++rt) {
            uint32_t ao = aoff0 + (uint32_t)(rt * 2304) + (uint32_t)(kk * 32);
            ldsm4(ah[rt], uAh + ao);
            ldsm4(al[rt], uAl + ao);
        }
        uint32_t bh[4][2], bl[4][2];
        #pragma unroll
        for (int t = 0; t < 2; ++t) {
            uint32_t bo = boff0 + (uint32_t)(t * 2304) + (uint32_t)(kk * 32);
            uint32_t rh[4], rl[4];
            ldsm4(rh, uBh + bo);
            ldsm4(rl, uBl + bo);
            bh[2 * t][0] = rh[0]; bh[2 * t][1] = rh[1];
            bh[2 * t + 1][0] = rh[2]; bh[2 * t + 1][1] = rh[3];
            bl[2 * t][0] = rl[0]; bl[2 * t][1] = rl[1];
            bl[2 * t + 1][0] = rl[2]; bl[2 * t + 1][1] = rl[3];
        }
        #pragma unroll
        for (int rt = 0; rt < 2; ++rt)
            #pragma unroll
            for (int nt = 0; nt < 4; ++nt) {
                mma16816(acc[rt][nt], ah[rt], bh[nt]);
                mma16816(acc[rt][nt], ah[rt], bl[nt]);
                mma16816(acc[rt][nt], al[rt], bh[nt]);
            }
    }
}

// ---------------- smem layout (dynamic, 54528 B -> 4 CTAs/SM) ----------------------
// [0,18432)      sAh  128x72 bf16
// [18432,36864)  sAl
// [36864,41472)  sBh   32x72 bf16
// [41472,46080)  sBl
// [46080,54528)  sEp   4 warps x (16x33 fp32 = 2112 B), two-pass epilogue
#define SMEM_BYTES 54528

// ---------------- stage kernel -----------------------------------------------------
template<int SB>
__global__ __launch_bounds__(128, 4) void stageK(const float* __restrict__ xin,
                                                 float* __restrict__ xout) {
    constexpr bool FIN  = (SB == 12);   // fp32 input (convert in loader)
    constexpr bool FOUT = (SB == 10);   // fp32 output
    constexpr int  TPC  = FIN ? 1 : 2;
    constexpr size_t OC = (size_t)1 << SB;

    extern __shared__ __align__(16) char smem[];
    __nv_bfloat16* sAh = (__nv_bfloat16*)(smem);
    __nv_bfloat16* sAl = (__nv_bfloat16*)(smem + 18432);
    __nv_bfloat16* sBh = (__nv_bfloat16*)(smem + 36864);
    __nv_bfloat16* sBl = (__nv_bfloat16*)(smem + 41472);
    float*         sEp = (float*)(smem + 46080);

    const __nv_bfloat16* inh = (SB == 11) ? g_T1h : g_T2h;
    const __nv_bfloat16* inl = (SB == 11) ? g_T1l : g_T2l;
    __nv_bfloat16* outh = (SB == 12) ? g_T1h : g_T2h;
    __nv_bfloat16* outl = (SB == 12) ? g_T1l : g_T2l;

    const int tid = threadIdx.x;
    const int w   = tid >> 5;
    const int lid = tid & 31;
    const int gid = lid >> 2;
    const int tg  = lid & 3;
    const int lr  = lid & 7, mi = lid >> 3;

    const uint32_t uAh = smem_u32(sAh), uAl = smem_u32(sAl);
    const uint32_t uBh = smem_u32(sBh), uBl = smem_u32(sBl);
    float* sEpW = sEp + w * 528;

    const uint32_t aoff0 =
        (uint32_t)(w * 32 + ((mi & 1) << 3) + lr) * 144u + ((mi >> 1) << 4);
    const uint32_t boff0 =
        (uint32_t)(((mi >> 1) << 3) + lr) * 144u + ((mi & 1) << 4);

    // ---- B staging
    {
        const uint32_t* bh = (const uint32_t*)g_Bh;
        const uint32_t* bl = (const uint32_t*)g_Bl;
        #pragma unroll
        for (int idx = tid; idx < 1024; idx += 128) {
            int r = idx >> 5, c2 = idx & 31;
            *(uint32_t*)&sBh[r * 72 + c2 * 2] = bh[idx];
            *(uint32_t*)&sBl[r * 72 + c2 * 2] = bl[idx];
        }
    }

    const int tt0 = blockIdx.x * TPC;
    float4 v[16];   // stage-1 register prefetch (used only when FIN)

    // ---- initial fill (tile tt0)
    if (FIN) {
        const float4* __restrict__ inp = (const float4*)(xin + (size_t)tt0 * 8192);
        #pragma unroll
        for (int j = 0; j < 16; ++j) v[j] = inp[j * 128 + tid];
        #pragma unroll
        for (int j = 0; j < 16; ++j) {
            int f = j * 128 + tid;
            int r = f >> 4, k4 = f & 15;
            uint32_t h01, h23, l01, l23;
            asm("cvt.rn.bf16x2.f32 %0, %1, %2;" : "=r"(h01) : "f"(v[j].y), "f"(v[j].x));
            asm("cvt.rn.bf16x2.f32 %0, %1, %2;" : "=r"(h23) : "f"(v[j].w), "f"(v[j].z));
            float hx = __uint_as_float(h01 << 16);
            float hy = __uint_as_float(h01 & 0xFFFF0000u);
            float hz = __uint_as_float(h23 << 16);
            float hw = __uint_as_float(h23 & 0xFFFF0000u);
            asm("cvt.rn.bf16x2.f32 %0, %1, %2;" : "=r"(l01)
                : "f"(v[j].y - hy), "f"(v[j].x - hx));
            asm("cvt.rn.bf16x2.f32 %0, %1, %2;" : "=r"(l23)
                : "f"(v[j].w - hw), "f"(v[j].z - hz));
            *(uint2*)&sAh[r * 72 + k4 * 4] = make_uint2(h01, h23);
            *(uint2*)&sAl[r * 72 + k4 * 4] = make_uint2(l01, l23);
        }
    } else {
        const char* ph = (const char*)inh + (size_t)tt0 * 16384;
        const char* pl = (const char*)inl + (size_t)tt0 * 16384;
        #pragma unroll
        for (int j = 0; j < 8; ++j) {
            int f = j * 128 + tid;
            uint32_t d = (uint32_t)(f >> 3) * 144u + (uint32_t)(f & 7) * 16u;
            cp16(uAh + d, ph + (size_t)f * 16);
            cp16(uAl + d, pl + (size_t)f * 16);
        }
        CP_COMMIT();
        CP_WAIT0();
    }
    __syncthreads();

    #pragma unroll
    for (int i = 0; i < TPC; ++i) {
        const int tt = tt0 + i;

        float acc[2][4][4];
        mainloop128(acc, uAh, uAl, uBh, uBl, aoff0, boff0);
        __syncthreads();    // all ldsm done; A-buf free for prefetch

        // ---- prefetch next tile (overlaps epilogue below)
        if (!FIN && i + 1 < TPC) {
            const int tn = tt + 1;
            const char* ph = (const char*)inh + (size_t)tn * 16384;
            const char* pl = (const char*)inl + (size_t)tn * 16384;
            #pragma unroll
            for (int j = 0; j < 8; ++j) {
                int f = j * 128 + tid;
                uint32_t d = (uint32_t)(f >> 3) * 144u + (uint32_t)(f & 7) * 16u;
                cp16(uAh + d, ph + (size_t)f * 16);
                cp16(uAl + d, pl + (size_t)f * 16);
            }
            CP_COMMIT();
        }

        // ---- epilogue: two 16-row passes through per-warp ep buffer
        const size_t M0 = (size_t)tt * 128;
        const size_t obase = (M0 >> SB) * (OC * 32) + (M0 & (OC - 1));

        #pragma unroll
        for (int p = 0; p < 2; ++p) {
            __syncwarp();
            #pragma unroll
            for (int nt = 0; nt < 4; ++nt)
                #pragma unroll
                for (int q = 0; q < 4; ++q) {
                    int r0 = gid + ((q >> 1) << 3);
                    int c  = nt * 8 + tg * 2 + (q & 1);
                    sEpW[r0 * 33 + c] = acc[p][nt][q];
                }
            __syncwarp();

            if (FOUT) {
                #pragma unroll
                for (int jj = 0; jj < 16; ++jj) {
                    int item = jj * 32 + lid;
                    int c = item >> 4, ml = item & 15;
                    xout[obase + (size_t)c * OC
                         + (size_t)(w * 32 + p * 16 + ml)] = sEpW[ml * 33 + c];
                }
            } else {
                uint32_t* OH = (uint32_t*)outh;
                uint32_t* OL = (uint32_t*)outl;
                #pragma unroll
                for (int jj = 0; jj < 8; ++jj) {
                    int item = jj * 32 + lid;
                    int c = item >> 3, mp = item & 7;
                    float v0 = sEpW[(2 * mp) * 33 + c];
                    float v1 = sEpW[(2 * mp + 1) * 33 + c];
                    uint32_t pH;
                    asm("cvt.rn.bf16x2.f32 %0, %1, %2;" : "=r"(pH)
                        : "f"(v1), "f"(v0));
                    float h0 = __uint_as_float(pH << 16);
                    float h1 = __uint_as_float(pH & 0xFFFF0000u);
                    uint32_t pL;
                    asm("cvt.rn.bf16x2.f32 %0, %1, %2;" : "=r"(pL)
                        : "f"(v1 - h1), "f"(v0 - h0));
                    size_t word = (obase + (size_t)c * OC
                                   + (size_t)(w * 32 + p * 16 + 2 * mp)) >> 1;
                    OH[word] = pH;
                    OL[word] = pL;
                }
            }
        }

        // ---- finish prefetch before next mainloop
        if (i + 1 < TPC) {
            CP_WAIT0();
            __syncthreads();
        }
    }
}

// ---------------- launch ------------------------------------------------------------
extern "C" void kernel_launch(void* const* d_in, const int* in_sizes, int n_in,
                              void* d_out, int out_size) {
    const float* x = (const float*)d_in[0];
    float* out = (float*)d_out;

    cudaFuncSetAttribute(stageK<12>, cudaFuncAttributeMaxDynamicSharedMemorySize,
                         SMEM_BYTES);
    cudaFuncSetAttribute(stageK<11>, cudaFuncAttributeMaxDynamicSharedMemorySize,
                         SMEM_BYTES);
    cudaFuncSetAttribute(stageK<10>, cudaFuncAttributeMaxDynamicSharedMemorySize,
                         SMEM_BYTES);

    init_B_kernel<<<512, 128>>>();

    // tiles: stage1 = 1048576 rows/128 = 8192 (TPC=1);
    //        stage2 = 524288/128 = 4096 tiles -> 2048 CTAs (TPC=2);
    //        stage3 = 262144/128 = 2048 tiles -> 1024 CTAs (TPC=2).
    stageK<12><<<8192, 128, SMEM_BYTES>>>(x, out);  // X  -> T1 planes
    stageK<11><<<2048, 128, SMEM_BYTES>>>(x, out);  // T1 -> T2 planes
    stageK<10><<<1024, 128, SMEM_BYTES>>>(x, out);  // T2 -> Y (fp32)
}

// round 11
// speedup vs baseline: 1.1775x; 1.1404x over previous
#include <cuda_runtime.h>
#include <cuda_bf16.h>
#include <stdint.h>

// ----------------------------------------------------------------------------
// SpectralPooling via HMMA (mma.sync m16n8k16 bf16, 3-term split) GEMMs.
// y = idctn(pad(crop(dctn(x)))); axes 0,1 cancel. Per-axis operator
// B[o][i] = sum_{k<28} D32[k,o]*D64[k,i]  (32x64), applied along axes 2,3,4.
// Three stages, each GEMM [rows x 64] -> [rows x 32] against B^T; outputs are
// written "pre-transposed" so K is always contiguous and stores coalesce:
//   stage1 (SB=12): X[b][i0][i1][i2]   -> T1[b][o2][i0][i1]
//   stage2 (SB=11): T1[b][o2][i0][i1]  -> T2[b][o1][o2][i0]
//   stage3 (SB=10): T2[b][o1][o2][i0]  -> Y[b][o0][o1][o2]
// out_addr(m,c) = (m>>SB)*(32<<SB) + c*(1<<SB) + (m & ((1<<SB)-1))
// Precision: D = Ah*Bh + Ah*Bl + Al*Bh (bf16 hi/lo splits, fp32 accumulate).
// ldmatrix.x4 fragment loads; loader register peak capped (2 batches of 8
// float4) so ptxas fits 102 regs -> 5 CTAs/SM (register-limited before).
// ----------------------------------------------------------------------------

__device__ __nv_bfloat16 g_Bh[2048];   // B hi, row-major [o][i] (32x64)
__device__ __nv_bfloat16 g_Bl[2048];   // B lo
__device__ float g_T1[33554432];       // 128 MB scratch
__device__ float g_T2[16777216];       //  64 MB scratch

__device__ __forceinline__ uint32_t smem_u32(const void* p) {
    uint32_t a;
    asm("{ .reg .u64 t; cvta.to.shared.u64 t, %1; cvt.u32.u64 %0, t; }"
        : "=r"(a) : "l"(p));
    return a;
}

// ---------------- init: one warp per B element, lane = k-term -------------------
__global__ void init_B_kernel() {
    int gw   = (blockIdx.x * blockDim.x + threadIdx.x) >> 5;  // 0..2047
    int lane = threadIdx.x & 31;
    if (gw >= 2048) return;
    int o = gw >> 6;   // 0..31
    int i = gw & 63;   // 0..63
    float term = 0.0f;
    if (lane < 28) {
        const float s32_0 = 0.17677669529663688f;  // sqrt(1/32)
        const float s32_k = 0.25f;                 // sqrt(2/32)
        const float s64_0 = 0.125f;                // sqrt(1/64)
        const float s64_k = 0.17677669529663688f;  // sqrt(2/64)
        float a32 = (2.0f * o + 1.0f) * (float)lane / 64.0f;
        float a64 = (2.0f * i + 1.0f) * (float)lane / 128.0f;
        float d32 = ((lane == 0) ? s32_0 : s32_k) * cospif(a32);
        float d64 = ((lane == 0) ? s64_0 : s64_k) * cospif(a64);
        term = d32 * d64;
    }
    #pragma unroll
    for (int s = 16; s > 0; s >>= 1)
        term += __shfl_xor_sync(0xFFFFFFFFu, term, s);
    if (lane == 0) {
        __nv_bfloat16 h = __float2bfloat16(term);
        float lo = term - __bfloat162float(h);
        g_Bh[gw] = h;
        g_Bl[gw] = __float2bfloat16(lo);
    }
}

// ---------------- mma.sync / ldmatrix wrappers ------------------------------------
__device__ __forceinline__ void mma16816(float* d, const uint32_t* a,
                                         const uint32_t* b) {
    asm("mma.sync.aligned.m16n8k16.row.col.f32.bf16.bf16.f32 "
        "{%0,%1,%2,%3}, {%4,%5,%6,%7}, {%8,%9}, {%0,%1,%2,%3};"
        : "+f"(d[0]), "+f"(d[1]), "+f"(d[2]), "+f"(d[3])
        : "r"(a[0]), "r"(a[1]), "r"(a[2]), "r"(a[3]), "r"(b[0]), "r"(b[1]));
}

__device__ __forceinline__ void ldsm4(uint32_t* r, uint32_t addr) {
    asm volatile("ldmatrix.sync.aligned.m8n8.x4.shared.b16 {%0,%1,%2,%3}, [%4];"
                 : "=r"(r[0]), "=r"(r[1]), "=r"(r[2]), "=r"(r[3]) : "r"(addr));
}

// ---------------- stage kernel --------------------------------------------------
// A tile: 128 rows x 64 K (fp32 in, split to bf16 hi/lo in smem, stride 72 bf16).
// Warp w computes rows w*32..w*32+31, all 32 output cols.
template<int SB>
__global__ __launch_bounds__(128, 5) void stage_kernel(
        const float* __restrict__ xin, float* __restrict__ xout) {
    const float* in = (SB == 12) ? xin : (SB == 11 ? (const float*)g_T1
                                                   : (const float*)g_T2);
    float* out      = (SB == 12) ? (float*)g_T1
                                 : (SB == 11 ? (float*)g_T2 : xout);
    constexpr size_t OC = (size_t)1 << SB;

    __shared__ __align__(16) __nv_bfloat16 sAh[128 * 72];  // 18 KB
    __shared__ __align__(16) __nv_bfloat16 sAl[128 * 72];  // 18 KB
    __shared__ __align__(16) __nv_bfloat16 sBh[32 * 72];   // 4.5 KB
    __shared__ __align__(16) __nv_bfloat16 sBl[32 * 72];   // 4.5 KB

    const int tid = threadIdx.x;
    const int w   = tid >> 5;
    const int lid = tid & 31;
    const int gid = lid >> 2;   // 0..7
    const int tg  = lid & 3;    // 0..3

    // ---- load B hi/lo into padded smem (row stride 144 B)
    {
        const uint32_t* bh = (const uint32_t*)g_Bh;
        const uint32_t* bl = (const uint32_t*)g_Bl;
        #pragma unroll
        for (int idx = tid; idx < 1024; idx += 128) {
            int r = idx >> 5, c2 = idx & 31;
            *(uint32_t*)&sBh[r * 72 + c2 * 2] = bh[idx];
            *(uint32_t*)&sBl[r * 72 + c2 * 2] = bl[idx];
        }
    }

    // ---- load A tile (2048 float4) in 2 batches of 8 (bounded register peak)
    {
        const float4* __restrict__ inp =
            (const float4*)(in + (size_t)blockIdx.x * 8192);
        #pragma unroll 1
        for (int half = 0; half < 2; ++half) {
            float4 v[8];
            #pragma unroll
            for (int ji = 0; ji < 8; ++ji)
                v[ji] = inp[(half * 8 + ji) * 128 + tid];
            #pragma unroll
            for (int ji = 0; ji < 8; ++ji) {
                int f = (half * 8 + ji) * 128 + tid;
                int r = f >> 4, k4 = f & 15;
                uint32_t h01, h23, l01, l23;
                asm("cvt.rn.bf16x2.f32 %0, %1, %2;" : "=r"(h01)
                    : "f"(v[ji].y), "f"(v[ji].x));
                asm("cvt.rn.bf16x2.f32 %0, %1, %2;" : "=r"(h23)
                    : "f"(v[ji].w), "f"(v[ji].z));
                float hx = __uint_as_float(h01 << 16);
                float hy = __uint_as_float(h01 & 0xFFFF0000u);
                float hz = __uint_as_float(h23 << 16);
                float hw = __uint_as_float(h23 & 0xFFFF0000u);
                asm("cvt.rn.bf16x2.f32 %0, %1, %2;" : "=r"(l01)
                    : "f"(v[ji].y - hy), "f"(v[ji].x - hx));
                asm("cvt.rn.bf16x2.f32 %0, %1, %2;" : "=r"(l23)
                    : "f"(v[ji].w - hw), "f"(v[ji].z - hz));
                *(uint2*)&sAh[r * 72 + k4 * 4] = make_uint2(h01, h23);
                *(uint2*)&sAl[r * 72 + k4 * 4] = make_uint2(l01, l23);
            }
        }
    }
    __syncthreads();

    // ---- per-lane ldmatrix addressing
    // A (per rt, kk): matrices (mi&1 -> +8 rows, mi>>1 -> +8 k)
    // B (per t,  kk): matrices (mi>>1 -> +8 n,   mi&1  -> +8 k)
    const int lr = lid & 7, mi = lid >> 3;
    const uint32_t uAh = smem_u32(sAh), uAl = smem_u32(sAl);
    const uint32_t uBh = smem_u32(sBh), uBl = smem_u32(sBl);
    const uint32_t aoff0 =
        (uint32_t)(w * 32 + ((mi & 1) << 3) + lr) * 144u + ((mi >> 1) << 4);
    const uint32_t boff0 =
        (uint32_t)(((mi >> 1) << 3) + lr) * 144u + ((mi & 1) << 4);

    // ---- HMMA mainloop: acc[rt][nt][4]
    float acc[2][4][4];
    #pragma unroll
    for (int rt = 0; rt < 2; ++rt)
        #pragma unroll
        for (int nt = 0; nt < 4; ++nt)
            #pragma unroll
            for (int q = 0; q < 4; ++q) acc[rt][nt][q] = 0.0f;

    #pragma unroll
    for (int kk = 0; kk < 4; ++kk) {
        uint32_t ah[2][4], al[2][4];
        #pragma unroll
        for (int rt = 0; rt < 2; ++rt) {
            uint32_t ao = aoff0 + (uint32_t)(rt * 16 * 144) + (uint32_t)(kk * 32);
            ldsm4(ah[rt], uAh + ao);
            ldsm4(al[rt], uAl + ao);
        }
        // B: regs {b[2t][0], b[2t][1], b[2t+1][0], b[2t+1][1]} per ldsm4
        uint32_t bh[4][2], bl[4][2];
        #pragma unroll
        for (int t = 0; t < 2; ++t) {
            uint32_t bo = boff0 + (uint32_t)(t * 16 * 144) + (uint32_t)(kk * 32);
            uint32_t rh[4], rl[4];
            ldsm4(rh, uBh + bo);
            ldsm4(rl, uBl + bo);
            bh[2 * t][0] = rh[0]; bh[2 * t][1] = rh[1];
            bh[2 * t + 1][0] = rh[2]; bh[2 * t + 1][1] = rh[3];
            bl[2 * t][0] = rl[0]; bl[2 * t][1] = rl[1];
            bl[2 * t + 1][0] = rl[2]; bl[2 * t + 1][1] = rl[3];
        }
        #pragma unroll
        for (int rt = 0; rt < 2; ++rt)
            #pragma unroll
            for (int nt = 0; nt < 4; ++nt) {
                mma16816(acc[rt][nt], ah[rt], bh[nt]);   // Ah*Bh
                mma16816(acc[rt][nt], ah[rt], bl[nt]);   // Ah*Bl
                mma16816(acc[rt][nt], al[rt], bh[nt]);   // Al*Bh
            }
    }

    // ---- epilogue: transpose through this warp's own (dead) A region
    __syncwarp();
    float* epw = (float*)(sAh + (size_t)w * 32 * 72);   // 32x33 fp32 fits
    #pragma unroll
    for (int rt = 0; rt < 2; ++rt)
        #pragma unroll
        for (int nt = 0; nt < 4; ++nt) {
            int r0 = rt * 16 + gid;
            int c0 = nt * 8 + tg * 2;
            epw[r0 * 33 + c0]           = acc[rt][nt][0];
            epw[r0 * 33 + c0 + 1]       = acc[rt][nt][1];
            epw[(r0 + 8) * 33 + c0]     = acc[rt][nt][2];
            epw[(r0 + 8) * 33 + c0 + 1] = acc[rt][nt][3];
        }
    __syncwarp();

    // ---- coalesced transposed store
    size_t m = (size_t)blockIdx.x * 128 + (size_t)(w * 32 + lid);
    float* __restrict__ ob = out + (m >> SB) * (OC * 32) + (m & (OC - 1));
    #pragma unroll
    for (int c = 0; c < 32; ++c)
        ob[(size_t)c << SB] = epw[lid * 33 + c];
}

// ---------------- launch ---------------------------------------------------------
extern "C" void kernel_launch(void* const* d_in, const int* in_sizes, int n_in,
                              void* d_out, int out_size) {
    const float* x = (const float*)d_in[0];
    float* out = (float*)d_out;

    init_B_kernel<<<512, 128>>>();

    stage_kernel<12><<<8192, 128>>>(x, out);   // X  -> T1   (contract i2)
    stage_kernel<11><<<4096, 128>>>(x, out);   // T1 -> T2   (contract i1)
    stage_kernel<10><<<2048, 128>>>(x, out);   // T2 -> out  (contract i0)
}